// round 9
// baseline (speedup 1.0000x reference)
#include <cuda_runtime.h>

#define N_NODES 50000
#define N_EDGES 800000
#define D_FEAT  128
#define NUM_ITER 20
#define SCAN_BLOCKS ((N_NODES + 1023) / 1024)   // 49

// ---- device-global scratch (no dynamic allocation allowed) ----
__device__ float  g_buf [(size_t)N_NODES * D_FEAT];  // ping buffer
__device__ float  g_buf2[(size_t)N_NODES * D_FEAT];  // pong buffer
__device__ float2 g_colw[N_EDGES];                   // {col_bits, weight}, CSR order
__device__ int    g_counts[N_NODES];
__device__ int    g_row_ptr[N_NODES + 1];
__device__ int    g_cursor[N_NODES];
__device__ int    g_blocksum[SCAN_BLOCKS];
__device__ uint4  g_mask[N_NODES];                   // nonzero bitmask: word c bit lane = feature lane*4+c
__device__ int    g_is64;                            // 1 if edge_index is int64-layout

// ---------------- zero counts + dtype probe (fused) ----------------
__global__ void zero_detect_kernel(const int* __restrict__ ei32) {
    int i = blockIdx.x * blockDim.x + threadIdx.x;
    if (i < N_NODES) g_counts[i] = 0;
    if (blockIdx.x == 0 && threadIdx.x < 32) {
        bool nz = false;
        for (int k = threadIdx.x; k < 256; k += 32)
            if (ei32[2 * k + 1] != 0) nz = true;
        unsigned any = __ballot_sync(0xFFFFFFFFu, nz);
        if (threadIdx.x == 0) g_is64 = (any == 0) ? 1 : 0;
    }
}

__device__ __forceinline__ int load_idx(const void* ei, int pos) {
    if (g_is64) return (int)((const long long*)ei)[pos];
    return ((const int*)ei)[pos];
}

// ---------------- CSR build ----------------

__global__ void count_kernel(const void* __restrict__ ei) {
    int e = blockIdx.x * blockDim.x + threadIdx.x;
    if (e >= N_EDGES) return;
    int r = load_idx(ei, e);
    if ((unsigned)r < N_NODES) atomicAdd(&g_counts[r], 1);
}

// pass 1: per-tile exclusive scan + tile sums
__global__ void scan1_kernel() {
    __shared__ int sh[1024];
    int t = threadIdx.x;
    int gid = blockIdx.x * 1024 + t;
    int v = (gid < N_NODES) ? g_counts[gid] : 0;
    sh[t] = v;
    __syncthreads();
    for (int off = 1; off < 1024; off <<= 1) {
        int u = 0;
        if (t >= off) u = sh[t - off];
        __syncthreads();
        if (t >= off) sh[t] += u;
        __syncthreads();
    }
    if (gid < N_NODES) g_row_ptr[gid] = sh[t] - v;     // tile-local exclusive
    if (t == 1023) g_blocksum[blockIdx.x] = sh[t];
}

// pass 2 (fused): per-block parallel scan of the 49 tile sums + add offsets + init cursor
__global__ void scan3_kernel() {
    __shared__ int bs[64];
    int t = threadIdx.x;
    if (t < 64) bs[t] = (t < SCAN_BLOCKS) ? g_blocksum[t] : 0;
    __syncthreads();
    // inclusive scan of 64 entries (single warp-width-free shared scan)
    for (int off = 1; off < 64; off <<= 1) {
        int u = 0;
        if (t < 64 && t >= off) u = bs[t - off];
        __syncthreads();
        if (t < 64 && t >= off) bs[t] += u;
        __syncthreads();
    }
    int blockoff = (blockIdx.x == 0) ? 0 : bs[blockIdx.x - 1];
    int gid = blockIdx.x * 1024 + t;
    if (gid < N_NODES) {
        int v = g_row_ptr[gid] + blockoff;
        g_row_ptr[gid] = v;
        g_cursor[gid]  = v;
    }
    if (blockIdx.x == SCAN_BLOCKS - 1 && t == 0)
        g_row_ptr[N_NODES] = bs[SCAN_BLOCKS - 1];
}

__global__ void fill_kernel(const void* __restrict__ ei,
                            const float* __restrict__ w) {
    int e = blockIdx.x * blockDim.x + threadIdx.x;
    if (e >= N_EDGES) return;
    int r = load_idx(ei, e);
    int c = load_idx(ei, N_EDGES + e);
    if ((unsigned)r >= N_NODES || (unsigned)c >= N_NODES) return;
    int pos = atomicAdd(&g_cursor[r], 1);
    g_colw[pos] = make_float2(__int_as_float(c), w[e]);
}

// ---------------- nonzero bitmask of x + seed both buffers' masked positions ----
__global__ void maskbuild_kernel(const float* __restrict__ x,
                                 float* __restrict__ b0p,
                                 float* __restrict__ b1p) {
    int warp = (blockIdx.x * blockDim.x + threadIdx.x) >> 5;
    int lane = threadIdx.x & 31;
    if (warp >= N_NODES) return;
    float4 xv = ((const float4*)(x + (size_t)warp * D_FEAT))[lane];
    unsigned m0 = __ballot_sync(0xFFFFFFFFu, xv.x != 0.f);
    unsigned m1 = __ballot_sync(0xFFFFFFFFu, xv.y != 0.f);
    unsigned m2 = __ballot_sync(0xFFFFFFFFu, xv.z != 0.f);
    unsigned m3 = __ballot_sync(0xFFFFFFFFu, xv.w != 0.f);
    if (lane == 0) g_mask[warp] = make_uint4(m0, m1, m2, m3);
    // seed masked (nonzero-x) positions of both ping-pong buffers with x;
    // predicated SpMM iterations never rewrite these.
    size_t base = (size_t)warp * D_FEAT + lane * 4;
    if (xv.x != 0.f) { b0p[base + 0] = xv.x; b1p[base + 0] = xv.x; }
    if (xv.y != 0.f) { b0p[base + 1] = xv.y; b1p[base + 1] = xv.y; }
    if (xv.z != 0.f) { b0p[base + 2] = xv.z; b1p[base + 2] = xv.z; }
    if (xv.w != 0.f) { b0p[base + 3] = xv.w; b1p[base + 3] = xv.w; }
}

// ---------------- propagation: one warp per destination row ----------------
// MODE 0: full write — read x, write all 128 features (mask-select). (final iter)
// MODE 1: predicated — read 16B bitmask, write only zero positions.

template <int MODE>
__global__ __launch_bounds__(256)
void spmm_kernel(const float* __restrict__ in,
                 const float* __restrict__ x,
                 float* __restrict__ out) {
    int warp = (blockIdx.x * blockDim.x + threadIdx.x) >> 5;
    int lane = threadIdx.x & 31;
    if (warp >= N_NODES) return;

    int s = g_row_ptr[warp];
    int e = g_row_ptr[warp + 1];

    float4 acc0 = make_float4(0.f, 0.f, 0.f, 0.f);
    float4 acc1 = make_float4(0.f, 0.f, 0.f, 0.f);
    float4 acc2 = make_float4(0.f, 0.f, 0.f, 0.f);
    float4 acc3 = make_float4(0.f, 0.f, 0.f, 0.f);

    int i = s;
    for (; i + 4 <= e; i += 4) {             // 4 independent L2 row-gathers in flight
        float2 cw0 = g_colw[i];
        float2 cw1 = g_colw[i + 1];
        float2 cw2 = g_colw[i + 2];
        float2 cw3 = g_colw[i + 3];
        const float4* s0 = (const float4*)(in + (size_t)__float_as_int(cw0.x) * D_FEAT);
        const float4* s1 = (const float4*)(in + (size_t)__float_as_int(cw1.x) * D_FEAT);
        const float4* s2 = (const float4*)(in + (size_t)__float_as_int(cw2.x) * D_FEAT);
        const float4* s3 = (const float4*)(in + (size_t)__float_as_int(cw3.x) * D_FEAT);
        float4 v0 = s0[lane];
        float4 v1 = s1[lane];
        float4 v2 = s2[lane];
        float4 v3 = s3[lane];
        acc0.x += cw0.y * v0.x; acc0.y += cw0.y * v0.y;
        acc0.z += cw0.y * v0.z; acc0.w += cw0.y * v0.w;
        acc1.x += cw1.y * v1.x; acc1.y += cw1.y * v1.y;
        acc1.z += cw1.y * v1.z; acc1.w += cw1.y * v1.w;
        acc2.x += cw2.y * v2.x; acc2.y += cw2.y * v2.y;
        acc2.z += cw2.y * v2.z; acc2.w += cw2.y * v2.w;
        acc3.x += cw3.y * v3.x; acc3.y += cw3.y * v3.y;
        acc3.z += cw3.y * v3.z; acc3.w += cw3.y * v3.w;
    }
    for (; i < e; i++) {
        float2 cw0 = g_colw[i];
        const float4* s0 = (const float4*)(in + (size_t)__float_as_int(cw0.x) * D_FEAT);
        float4 v0 = s0[lane];
        acc0.x += cw0.y * v0.x; acc0.y += cw0.y * v0.y;
        acc0.z += cw0.y * v0.z; acc0.w += cw0.y * v0.w;
    }

    acc0.x += acc1.x; acc0.y += acc1.y; acc0.z += acc1.z; acc0.w += acc1.w;
    acc2.x += acc3.x; acc2.y += acc3.y; acc2.z += acc3.z; acc2.w += acc3.w;
    acc0.x += acc2.x; acc0.y += acc2.y; acc0.z += acc2.z; acc0.w += acc2.w;

    if (MODE == 0) {
        float4 xv = ((const float4*)(x + (size_t)warp * D_FEAT))[lane];
        float4 o;
        o.x = (xv.x != 0.f) ? xv.x : acc0.x;
        o.y = (xv.y != 0.f) ? xv.y : acc0.y;
        o.z = (xv.z != 0.f) ? xv.z : acc0.z;
        o.w = (xv.w != 0.f) ? xv.w : acc0.w;
        ((float4*)(out + (size_t)warp * D_FEAT))[lane] = o;
    } else {
        uint4 mw = g_mask[warp];
        float* orow = out + (size_t)warp * D_FEAT + lane * 4;
        if (!((mw.x >> lane) & 1u)) orow[0] = acc0.x;
        if (!((mw.y >> lane) & 1u)) orow[1] = acc0.y;
        if (!((mw.z >> lane) & 1u)) orow[2] = acc0.z;
        if (!((mw.w >> lane) & 1u)) orow[3] = acc0.w;
    }
}

// ---------------- launcher (graph-capturable, allocation-free) ----------------

extern "C" void kernel_launch(void* const* d_in, const int* in_sizes, int n_in,
                              void* d_out, int out_size) {
    const float* x  = (const float*)d_in[0];
    const void*  ei = d_in[1];                 // [2, E] int32 (JAX x64 off) or int64
    const float* w  = (const float*)d_in[2];
    float* out = (float*)d_out;

    float *buf = nullptr, *buf2 = nullptr;
    cudaGetSymbolAddress((void**)&buf,  g_buf);
    cudaGetSymbolAddress((void**)&buf2, g_buf2);

    zero_detect_kernel<<<(N_NODES + 255) / 256, 256>>>((const int*)ei);
    count_kernel<<<(N_EDGES + 255) / 256, 256>>>(ei);
    scan1_kernel<<<SCAN_BLOCKS, 1024>>>();
    scan3_kernel<<<SCAN_BLOCKS, 1024>>>();
    fill_kernel<<<(N_EDGES + 255) / 256, 256>>>(ei, w);
    maskbuild_kernel<<<(N_NODES * 32 + 255) / 256, 256>>>(x, buf, buf2);

    const int spmm_blocks = (N_NODES * 32 + 255) / 256;  // one warp per row
    // iters 0..18: predicated (masked positions pre-seeded with x in both buffers);
    // iter 19: full write -> d_out (poisoned by harness).
    const float* cur_in = x;
    for (int it = 0; it < NUM_ITER; it++) {
        float* cur_out = (it == NUM_ITER - 1) ? out
                       : (((it & 1) == 0) ? buf : buf2);
        if (it == NUM_ITER - 1)
            spmm_kernel<0><<<spmm_blocks, 256>>>(cur_in, x, cur_out);
        else
            spmm_kernel<1><<<spmm_blocks, 256>>>(cur_in, x, cur_out);
        cur_in = cur_out;
    }
}

// round 10
// speedup vs baseline: 1.0358x; 1.0358x over previous
#include <cuda_runtime.h>

#define N_NODES 50000
#define N_EDGES 800000
#define D_FEAT  128
#define NUM_ITER 20
#define SCAN_BLOCKS ((N_NODES + 1023) / 1024)   // 49

// ---- device-global scratch (no dynamic allocation allowed) ----
__device__ float  g_buf [(size_t)N_NODES * D_FEAT];  // ping buffer
__device__ float  g_buf2[(size_t)N_NODES * D_FEAT];  // pong buffer
__device__ float2 g_colw[N_EDGES];                   // {col_bits, weight}, CSR order
__device__ int    g_counts[N_NODES];
__device__ int    g_row_ptr[N_NODES + 1];
__device__ int    g_cursor[N_NODES];
__device__ int    g_blocksum[SCAN_BLOCKS];
__device__ uint4  g_mask[N_NODES];                   // nonzero bitmask: word c bit lane = feature lane*4+c
__device__ int    g_is64;                            // 1 if edge_index is int64-layout

// ---------------- zero counts + dtype probe (fused) ----------------
__global__ void zero_detect_kernel(const int* __restrict__ ei32) {
    int i = blockIdx.x * blockDim.x + threadIdx.x;
    if (i < N_NODES) g_counts[i] = 0;
    if (blockIdx.x == 0 && threadIdx.x < 32) {
        bool nz = false;
        for (int k = threadIdx.x; k < 256; k += 32)
            if (ei32[2 * k + 1] != 0) nz = true;
        unsigned any = __ballot_sync(0xFFFFFFFFu, nz);
        if (threadIdx.x == 0) g_is64 = (any == 0) ? 1 : 0;
    }
}

__device__ __forceinline__ int load_idx(const void* ei, int pos) {
    if (g_is64) return (int)((const long long*)ei)[pos];
    return ((const int*)ei)[pos];
}

// ---------------- CSR build ----------------

__global__ void count_kernel(const void* __restrict__ ei) {
    int e = blockIdx.x * blockDim.x + threadIdx.x;
    if (e >= N_EDGES) return;
    int r = load_idx(ei, e);
    if ((unsigned)r < N_NODES) atomicAdd(&g_counts[r], 1);
}

// pass 1: per-tile exclusive scan + tile sums
__global__ void scan1_kernel() {
    __shared__ int sh[1024];
    int t = threadIdx.x;
    int gid = blockIdx.x * 1024 + t;
    int v = (gid < N_NODES) ? g_counts[gid] : 0;
    sh[t] = v;
    __syncthreads();
    for (int off = 1; off < 1024; off <<= 1) {
        int u = 0;
        if (t >= off) u = sh[t - off];
        __syncthreads();
        if (t >= off) sh[t] += u;
        __syncthreads();
    }
    if (gid < N_NODES) g_row_ptr[gid] = sh[t] - v;     // tile-local exclusive
    if (t == 1023) g_blocksum[blockIdx.x] = sh[t];
}

// pass 2 (fused): per-block parallel scan of the 49 tile sums + add offsets + init cursor
__global__ void scan3_kernel() {
    __shared__ int bs[64];
    int t = threadIdx.x;
    if (t < 64) bs[t] = (t < SCAN_BLOCKS) ? g_blocksum[t] : 0;
    __syncthreads();
    for (int off = 1; off < 64; off <<= 1) {
        int u = 0;
        if (t < 64 && t >= off) u = bs[t - off];
        __syncthreads();
        if (t < 64 && t >= off) bs[t] += u;
        __syncthreads();
    }
    int blockoff = (blockIdx.x == 0) ? 0 : bs[blockIdx.x - 1];
    int gid = blockIdx.x * 1024 + t;
    if (gid < N_NODES) {
        int v = g_row_ptr[gid] + blockoff;
        g_row_ptr[gid] = v;
        g_cursor[gid]  = v;
    }
    if (blockIdx.x == SCAN_BLOCKS - 1 && t == 0)
        g_row_ptr[N_NODES] = bs[SCAN_BLOCKS - 1];
}

__global__ void fill_kernel(const void* __restrict__ ei,
                            const float* __restrict__ w) {
    int e = blockIdx.x * blockDim.x + threadIdx.x;
    if (e >= N_EDGES) return;
    int r = load_idx(ei, e);
    int c = load_idx(ei, N_EDGES + e);
    if ((unsigned)r >= N_NODES || (unsigned)c >= N_NODES) return;
    int pos = atomicAdd(&g_cursor[r], 1);
    g_colw[pos] = make_float2(__int_as_float(c), w[e]);
}

// ---------------- propagation: one warp per destination row ----------------
// MODE 0: full write — read x, write all 128 features (mask-select).
//         BUILD_MASK additionally stores the nonzero bitmask (iter 0 only).
// MODE 1: predicated — read 16B bitmask, write only zero positions
//         (masked positions already hold x in the target buffer).

template <int MODE, bool BUILD_MASK>
__global__ __launch_bounds__(256)
void spmm_kernel(const float* __restrict__ in,
                 const float* __restrict__ x,
                 float* __restrict__ out) {
    int warp = (blockIdx.x * blockDim.x + threadIdx.x) >> 5;
    int lane = threadIdx.x & 31;
    if (warp >= N_NODES) return;

    int s = g_row_ptr[warp];
    int e = g_row_ptr[warp + 1];

    float4 acc0 = make_float4(0.f, 0.f, 0.f, 0.f);
    float4 acc1 = make_float4(0.f, 0.f, 0.f, 0.f);
    float4 acc2 = make_float4(0.f, 0.f, 0.f, 0.f);
    float4 acc3 = make_float4(0.f, 0.f, 0.f, 0.f);

    int i = s;
    for (; i + 4 <= e; i += 4) {             // 4 independent L2 row-gathers in flight
        float2 cw0 = g_colw[i];
        float2 cw1 = g_colw[i + 1];
        float2 cw2 = g_colw[i + 2];
        float2 cw3 = g_colw[i + 3];
        const float4* s0 = (const float4*)(in + (size_t)__float_as_int(cw0.x) * D_FEAT);
        const float4* s1 = (const float4*)(in + (size_t)__float_as_int(cw1.x) * D_FEAT);
        const float4* s2 = (const float4*)(in + (size_t)__float_as_int(cw2.x) * D_FEAT);
        const float4* s3 = (const float4*)(in + (size_t)__float_as_int(cw3.x) * D_FEAT);
        float4 v0 = s0[lane];
        float4 v1 = s1[lane];
        float4 v2 = s2[lane];
        float4 v3 = s3[lane];
        acc0.x += cw0.y * v0.x; acc0.y += cw0.y * v0.y;
        acc0.z += cw0.y * v0.z; acc0.w += cw0.y * v0.w;
        acc1.x += cw1.y * v1.x; acc1.y += cw1.y * v1.y;
        acc1.z += cw1.y * v1.z; acc1.w += cw1.y * v1.w;
        acc2.x += cw2.y * v2.x; acc2.y += cw2.y * v2.y;
        acc2.z += cw2.y * v2.z; acc2.w += cw2.y * v2.w;
        acc3.x += cw3.y * v3.x; acc3.y += cw3.y * v3.y;
        acc3.z += cw3.y * v3.z; acc3.w += cw3.y * v3.w;
    }
    for (; i < e; i++) {
        float2 cw0 = g_colw[i];
        const float4* s0 = (const float4*)(in + (size_t)__float_as_int(cw0.x) * D_FEAT);
        float4 v0 = s0[lane];
        acc0.x += cw0.y * v0.x; acc0.y += cw0.y * v0.y;
        acc0.z += cw0.y * v0.z; acc0.w += cw0.y * v0.w;
    }

    acc0.x += acc1.x; acc0.y += acc1.y; acc0.z += acc1.z; acc0.w += acc1.w;
    acc2.x += acc3.x; acc2.y += acc3.y; acc2.z += acc3.z; acc2.w += acc3.w;
    acc0.x += acc2.x; acc0.y += acc2.y; acc0.z += acc2.z; acc0.w += acc2.w;

    if (MODE == 0) {
        float4 xv = ((const float4*)(x + (size_t)warp * D_FEAT))[lane];
        if (BUILD_MASK) {
            unsigned m0 = __ballot_sync(0xFFFFFFFFu, xv.x != 0.f);
            unsigned m1 = __ballot_sync(0xFFFFFFFFu, xv.y != 0.f);
            unsigned m2 = __ballot_sync(0xFFFFFFFFu, xv.z != 0.f);
            unsigned m3 = __ballot_sync(0xFFFFFFFFu, xv.w != 0.f);
            if (lane == 0) g_mask[warp] = make_uint4(m0, m1, m2, m3);
        }
        float4 o;
        o.x = (xv.x != 0.f) ? xv.x : acc0.x;
        o.y = (xv.y != 0.f) ? xv.y : acc0.y;
        o.z = (xv.z != 0.f) ? xv.z : acc0.z;
        o.w = (xv.w != 0.f) ? xv.w : acc0.w;
        ((float4*)(out + (size_t)warp * D_FEAT))[lane] = o;
    } else {
        uint4 mw = g_mask[warp];
        float* orow = out + (size_t)warp * D_FEAT + lane * 4;
        if (!((mw.x >> lane) & 1u)) orow[0] = acc0.x;
        if (!((mw.y >> lane) & 1u)) orow[1] = acc0.y;
        if (!((mw.z >> lane) & 1u)) orow[2] = acc0.z;
        if (!((mw.w >> lane) & 1u)) orow[3] = acc0.w;
    }
}

// ---------------- launcher (graph-capturable, allocation-free) ----------------

extern "C" void kernel_launch(void* const* d_in, const int* in_sizes, int n_in,
                              void* d_out, int out_size) {
    const float* x  = (const float*)d_in[0];
    const void*  ei = d_in[1];                 // [2, E] int32 (JAX x64 off) or int64
    const float* w  = (const float*)d_in[2];
    float* out = (float*)d_out;

    float *buf = nullptr, *buf2 = nullptr;
    cudaGetSymbolAddress((void**)&buf,  g_buf);
    cudaGetSymbolAddress((void**)&buf2, g_buf2);

    zero_detect_kernel<<<(N_NODES + 255) / 256, 256>>>((const int*)ei);
    count_kernel<<<(N_EDGES + 255) / 256, 256>>>(ei);
    scan1_kernel<<<SCAN_BLOCKS, 1024>>>();
    scan3_kernel<<<SCAN_BLOCKS, 1024>>>();
    fill_kernel<<<(N_EDGES + 255) / 256, 256>>>(ei, w);

    const int spmm_blocks = (N_NODES * 32 + 255) / 256;  // one warp per row
    // iter 0: full write + mask build -> buf ; iter 1: full write -> buf2 ;
    // iters 2..18: predicated ping-pong ; iter 19: full write -> d_out.
    const float* cur_in = x;
    for (int it = 0; it < NUM_ITER; it++) {
        float* cur_out = (it == NUM_ITER - 1) ? out
                       : (((it & 1) == 0) ? buf : buf2);
        if (it == 0)
            spmm_kernel<0, true ><<<spmm_blocks, 256>>>(cur_in, x, cur_out);
        else if (it == 1 || it == NUM_ITER - 1)
            spmm_kernel<0, false><<<spmm_blocks, 256>>>(cur_in, x, cur_out);
        else
            spmm_kernel<1, false><<<spmm_blocks, 256>>>(cur_in, x, cur_out);
        cur_in = cur_out;
    }
}